// round 8
// baseline (speedup 1.0000x reference)
#include <cuda_runtime.h>

#define Nn 16384
#define HIDD 64
#define Kk 16
#define TJ 32

// ---------------- device scratch (no allocs allowed) ----------------
__device__ __align__(16) float g_B1[Nn * HIDD];
__device__ __align__(16) float g_C1[Nn * HIDD];
__device__ __align__(16) float g_x1[Nn * HIDD];
__device__ __align__(16) float g_B2[Nn * HIDD];
__device__ __align__(16) float g_C2[Nn * HIDD];
__device__ __align__(16) float g_sq[Nn];
__device__ int g_knn[Nn * Kk];
__device__ int g_is64;

// ---------------- edge_index dtype detection (int32 vs int64) ----------------
__global__ void detect_kernel(const int* __restrict__ ei32) {
    __shared__ int anynz;
    if (threadIdx.x == 0) anynz = 0;
    __syncthreads();
    // If data is int64 (values < 2^31, nonneg), every odd 32-bit word is 0.
    for (int t = threadIdx.x; t < 2048; t += blockDim.x) {
        if (ei32[2 * t + 1] != 0) anynz = 1;
    }
    __syncthreads();
    if (threadIdx.x == 0) g_is64 = (anynz == 0) ? 1 : 0;
}

// ---------------- init x1 = 0 (segment_max fill + relu>=0 makes this exact) ----------------
__global__ void zero_x1() {
    int t = blockIdx.x * blockDim.x + threadIdx.x;
    if (t < Nn * HIDD) g_x1[t] = 0.f;
}

// ---------------- stage-1 per-node precompute ----------------
// A[i] = xi @ W1[0:3], B[i] = xi @ W1[3:6], C1 = A - B + b1
__global__ void p1_kernel(const float* __restrict__ x, const float* __restrict__ W1,
                          const float* __restrict__ b1) {
    int t = blockIdx.x * blockDim.x + threadIdx.x;
    if (t >= Nn * HIDD) return;
    int i = t >> 6, h = t & 63;
    float x0 = x[i * 3 + 0], x1v = x[i * 3 + 1], x2v = x[i * 3 + 2];
    float a = x0 * W1[0 * HIDD + h] + x1v * W1[1 * HIDD + h] + x2v * W1[2 * HIDD + h];
    float b = x0 * W1[3 * HIDD + h] + x1v * W1[4 * HIDD + h] + x2v * W1[5 * HIDD + h];
    g_B1[t] = b;
    g_C1[t] = a - b + b1[h];
}

// ---------------- stage-1 per-edge: h=relu(C1[dst]+B1[src]); out=relu(h@W2+b2); atomicMax ----------------
__global__ void __launch_bounds__(128) e1_kernel(const void* __restrict__ eiv,
                                                 const float* __restrict__ W2,
                                                 const float* __restrict__ b2, int nE) {
    __shared__ float W2T[HIDD * HIDD];  // W2T[c][h] = W2[h][c]
    __shared__ float b2s[HIDD];
    for (int t = threadIdx.x; t < HIDD * HIDD; t += blockDim.x) {
        int hh = t >> 6, c = t & 63;
        W2T[c * HIDD + hh] = W2[t];
    }
    if (threadIdx.x < HIDD) b2s[threadIdx.x] = b2[threadIdx.x];
    __syncthreads();

    int e = blockIdx.x * blockDim.x + threadIdx.x;
    if (e >= nE) return;
    int src, dst;
    if (g_is64) {
        const int* e32 = (const int*)eiv;            // low words of little-endian int64
        src = e32[2 * e];
        dst = e32[2 * (nE + e)];
    } else {
        const int* e32 = (const int*)eiv;
        src = e32[e];
        dst = e32[nE + e];
    }

    float h[HIDD];
    const float4* Cv = (const float4*)(g_C1 + dst * HIDD);
    const float4* Bv = (const float4*)(g_B1 + src * HIDD);
#pragma unroll
    for (int q = 0; q < 16; q++) {
        float4 c4 = Cv[q], b4v = Bv[q];
        h[4 * q + 0] = fmaxf(c4.x + b4v.x, 0.f);
        h[4 * q + 1] = fmaxf(c4.y + b4v.y, 0.f);
        h[4 * q + 2] = fmaxf(c4.z + b4v.z, 0.f);
        h[4 * q + 3] = fmaxf(c4.w + b4v.w, 0.f);
    }

    int* xo = (int*)(g_x1 + dst * HIDD);
    for (int c = 0; c < HIDD; c++) {
        const float4* w = (const float4*)(W2T + c * HIDD);
        float a0 = 0.f, a1 = 0.f, a2 = 0.f, a3 = 0.f;
#pragma unroll
        for (int q = 0; q < 16; q++) {
            float4 ww = w[q];
            a0 += h[4 * q + 0] * ww.x;
            a1 += h[4 * q + 1] * ww.y;
            a2 += h[4 * q + 2] * ww.z;
            a3 += h[4 * q + 3] * ww.w;
        }
        float v = (a0 + a1) + (a2 + a3) + b2s[c];
        // relu + max: x1 init'd to 0, post-ReLU values >= 0 => int atomicMax is order-preserving
        if (v > 0.f) atomicMax(xo + c, __float_as_int(v));
    }
}

// ---------------- row squared norms of x1 (same reduction pattern as knn dot => exact 0 self-dist) ----------------
__global__ void sq_kernel() {
    int i = blockIdx.x * blockDim.x + threadIdx.x;
    if (i >= Nn) return;
    const float4* xv = (const float4*)(g_x1 + i * HIDD);
    float a0 = 0.f, a1 = 0.f, a2 = 0.f, a3 = 0.f;
#pragma unroll
    for (int q = 0; q < 16; q++) {
        float4 v = xv[q];
        a0 += v.x * v.x;
        a1 += v.y * v.y;
        a2 += v.z * v.z;
        a3 += v.w * v.w;
    }
    g_sq[i] = (a0 + a1) + (a2 + a3);
}

// ---------------- brute-force kNN (k=16 incl. self), register top-k ----------------
__global__ void __launch_bounds__(128) knn_kernel() {
    __shared__ float xs[TJ * HIDD];
    __shared__ float sqs[TJ];
    int i = blockIdx.x * blockDim.x + threadIdx.x;  // one row per thread

    float xi[HIDD];
    {
        const float4* xv = (const float4*)(g_x1 + i * HIDD);
#pragma unroll
        for (int q = 0; q < 16; q++) {
            float4 v = xv[q];
            xi[4 * q + 0] = v.x;
            xi[4 * q + 1] = v.y;
            xi[4 * q + 2] = v.z;
            xi[4 * q + 3] = v.w;
        }
    }
    float sqi = g_sq[i];

    float bd[Kk];
    int bi[Kk];
#pragma unroll
    for (int m = 0; m < Kk; m++) {
        bd[m] = 3.4e38f;
        bi[m] = 0;
    }
    float worst = 3.4e38f;

    for (int j0 = 0; j0 < Nn; j0 += TJ) {
        __syncthreads();
        {
            const float4* srcp = (const float4*)(g_x1 + j0 * HIDD);
            float4* dstp = (float4*)xs;
            for (int t = threadIdx.x; t < TJ * HIDD / 4; t += blockDim.x) dstp[t] = srcp[t];
            if (threadIdx.x < TJ) sqs[threadIdx.x] = g_sq[j0 + threadIdx.x];
        }
        __syncthreads();

#pragma unroll 2
        for (int jj = 0; jj < TJ; jj++) {
            const float4* xj = (const float4*)(xs + jj * HIDD);
            float a0 = 0.f, a1 = 0.f, a2 = 0.f, a3 = 0.f;
#pragma unroll
            for (int q = 0; q < 16; q++) {
                float4 v = xj[q];
                a0 += xi[4 * q + 0] * v.x;
                a1 += xi[4 * q + 1] * v.y;
                a2 += xi[4 * q + 2] * v.z;
                a3 += xi[4 * q + 3] * v.w;
            }
            float d = sqi + sqs[jj] - 2.f * ((a0 + a1) + (a2 + a3));
            if (d < worst) {
                // sorted (ascending) register insertion; strict < keeps earlier j on ties
                float cd = d;
                int cj = j0 + jj;
#pragma unroll
                for (int m = 0; m < Kk; m++) {
                    if (cd < bd[m]) {
                        float td = bd[m];
                        bd[m] = cd;
                        cd = td;
                        int ti = bi[m];
                        bi[m] = cj;
                        cj = ti;
                    }
                }
                worst = bd[Kk - 1];
            }
        }
    }
#pragma unroll
    for (int m = 0; m < Kk; m++) g_knn[i * Kk + m] = bi[m];
}

// ---------------- stage-2 per-node precompute on x1 ----------------
__global__ void p2_kernel(const float* __restrict__ W3, const float* __restrict__ b3) {
    int t = blockIdx.x * blockDim.x + threadIdx.x;
    if (t >= Nn * HIDD) return;
    int i = t >> 6, h = t & 63;
    const float* xr = g_x1 + i * HIDD;
    float a = 0.f, b = 0.f;
#pragma unroll 8
    for (int c = 0; c < HIDD; c++) {
        float xc = xr[c];
        a += xc * W3[c * HIDD + h];
        b += xc * W3[(HIDD + c) * HIDD + h];
    }
    g_B2[t] = b;
    g_C2[t] = a - b + b3[h];
}

// ---------------- stage-2 per-edge + max-aggregate (no atomics; shfl over 16-lane groups) ----------------
__global__ void __launch_bounds__(128) e2_kernel(const float* __restrict__ W4,
                                                 const float* __restrict__ b4,
                                                 float* __restrict__ out) {
    __shared__ float W4T[HIDD * HIDD];  // W4T[c][h] = W4[h][c]
    __shared__ float b4s[HIDD];
    for (int t = threadIdx.x; t < HIDD * HIDD; t += blockDim.x) {
        int hh = t >> 6, c = t & 63;
        W4T[c * HIDD + hh] = W4[t];
    }
    if (threadIdx.x < HIDD) b4s[threadIdx.x] = b4[threadIdx.x];
    __syncthreads();

    int lane = threadIdx.x & 31;
    int warp = (blockIdx.x * blockDim.x + threadIdx.x) >> 5;
    int node = warp * 2 + (lane >> 4);  // 2 nodes per warp
    int slot = lane & 15;               // neighbor slot within node
    int j = g_knn[node * Kk + slot];

    float h[HIDD];
    const float4* Cv = (const float4*)(g_C2 + node * HIDD);
    const float4* Bv = (const float4*)(g_B2 + j * HIDD);
#pragma unroll
    for (int q = 0; q < 16; q++) {
        float4 c4 = Cv[q], b4v = Bv[q];
        h[4 * q + 0] = fmaxf(c4.x + b4v.x, 0.f);
        h[4 * q + 1] = fmaxf(c4.y + b4v.y, 0.f);
        h[4 * q + 2] = fmaxf(c4.z + b4v.z, 0.f);
        h[4 * q + 3] = fmaxf(c4.w + b4v.w, 0.f);
    }

    for (int c = 0; c < HIDD; c++) {
        const float4* w = (const float4*)(W4T + c * HIDD);
        float a0 = 0.f, a1 = 0.f, a2 = 0.f, a3 = 0.f;
#pragma unroll
        for (int q = 0; q < 16; q++) {
            float4 ww = w[q];
            a0 += h[4 * q + 0] * ww.x;
            a1 += h[4 * q + 1] * ww.y;
            a2 += h[4 * q + 2] * ww.z;
            a3 += h[4 * q + 3] * ww.w;
        }
        float v = fmaxf((a0 + a1) + (a2 + a3) + b4s[c], 0.f);
        v = fmaxf(v, __shfl_xor_sync(0xffffffffu, v, 8));
        v = fmaxf(v, __shfl_xor_sync(0xffffffffu, v, 4));
        v = fmaxf(v, __shfl_xor_sync(0xffffffffu, v, 2));
        v = fmaxf(v, __shfl_xor_sync(0xffffffffu, v, 1));
        if (slot == 0) out[node * HIDD + c] = v;
    }
}

// ---------------- launch ----------------
extern "C" void kernel_launch(void* const* d_in, const int* in_sizes, int n_in,
                              void* d_out, int out_size) {
    const float* x = (const float*)d_in[0];
    const void* ei = d_in[1];
    // 'k' may or may not be materialized as input #2 (size-1 array); detect.
    int wb = (n_in > 2 && in_sizes[2] == 1) ? 3 : 2;
    const float* W1 = (const float*)d_in[wb + 0];
    const float* b1 = (const float*)d_in[wb + 1];
    const float* W2 = (const float*)d_in[wb + 2];
    const float* b2 = (const float*)d_in[wb + 3];
    const float* W3 = (const float*)d_in[wb + 4];
    const float* b3 = (const float*)d_in[wb + 5];
    const float* W4 = (const float*)d_in[wb + 6];
    const float* b4 = (const float*)d_in[wb + 7];
    int nE = in_sizes[1] / 2;

    detect_kernel<<<1, 256>>>((const int*)ei);
    zero_x1<<<(Nn * HIDD + 255) / 256, 256>>>();
    p1_kernel<<<(Nn * HIDD + 255) / 256, 256>>>(x, W1, b1);
    e1_kernel<<<(nE + 127) / 128, 128>>>(ei, W2, b2, nE);
    sq_kernel<<<(Nn + 127) / 128, 128>>>();
    knn_kernel<<<Nn / 128, 128>>>();
    p2_kernel<<<(Nn * HIDD + 255) / 256, 256>>>(W3, b3);
    e2_kernel<<<Nn / 8, 128>>>(W4, b4, (float*)d_out);
}

// round 9
// speedup vs baseline: 1.0027x; 1.0027x over previous
#include <cuda_runtime.h>

#define Nn 16384
#define HIDD 64
#define Kk 16
#define TJ 32

// ---------------- device scratch (no allocs allowed) ----------------
__device__ __align__(16) float g_B1[Nn * HIDD];
__device__ __align__(16) float g_C1[Nn * HIDD];
__device__ __align__(16) float g_x1[Nn * HIDD];
__device__ __align__(16) float g_B2[Nn * HIDD];
__device__ __align__(16) float g_C2[Nn * HIDD];
__device__ __align__(16) float g_sq[Nn];
__device__ int g_knn[Nn * Kk];
__device__ int g_is64;

// ---------------- edge_index dtype detection (int32 vs int64) ----------------
__global__ void detect_kernel(const int* __restrict__ ei32) {
    __shared__ int anynz;
    if (threadIdx.x == 0) anynz = 0;
    __syncthreads();
    // If data is int64 (values < 2^31, nonneg), every odd 32-bit word is 0.
    for (int t = threadIdx.x; t < 2048; t += blockDim.x) {
        if (ei32[2 * t + 1] != 0) anynz = 1;
    }
    __syncthreads();
    if (threadIdx.x == 0) g_is64 = (anynz == 0) ? 1 : 0;
}

// ---------------- init x1 = 0 (segment_max fill + relu>=0 makes this exact) ----------------
__global__ void zero_x1() {
    int t = blockIdx.x * blockDim.x + threadIdx.x;
    if (t < Nn * HIDD) g_x1[t] = 0.f;
}

// ---------------- stage-1 per-node precompute ----------------
// A[i] = xi @ W1[0:3], B[i] = xi @ W1[3:6], C1 = A - B + b1
__global__ void p1_kernel(const float* __restrict__ x, const float* __restrict__ W1,
                          const float* __restrict__ b1) {
    int t = blockIdx.x * blockDim.x + threadIdx.x;
    if (t >= Nn * HIDD) return;
    int i = t >> 6, h = t & 63;
    float x0 = x[i * 3 + 0], x1v = x[i * 3 + 1], x2v = x[i * 3 + 2];
    float a = x0 * W1[0 * HIDD + h] + x1v * W1[1 * HIDD + h] + x2v * W1[2 * HIDD + h];
    float b = x0 * W1[3 * HIDD + h] + x1v * W1[4 * HIDD + h] + x2v * W1[5 * HIDD + h];
    g_B1[t] = b;
    g_C1[t] = a - b + b1[h];
}

// ---------------- stage-1 per-edge: h=relu(C1[dst]+B1[src]); out=relu(h@W2+b2); atomicMax ----------------
__global__ void __launch_bounds__(128) e1_kernel(const void* __restrict__ eiv,
                                                 const float* __restrict__ W2,
                                                 const float* __restrict__ b2, int nE) {
    __shared__ float W2T[HIDD * HIDD];  // W2T[c][h] = W2[h][c]
    __shared__ float b2s[HIDD];
    for (int t = threadIdx.x; t < HIDD * HIDD; t += blockDim.x) {
        int hh = t >> 6, c = t & 63;
        W2T[c * HIDD + hh] = W2[t];
    }
    if (threadIdx.x < HIDD) b2s[threadIdx.x] = b2[threadIdx.x];
    __syncthreads();

    int e = blockIdx.x * blockDim.x + threadIdx.x;
    if (e >= nE) return;
    int src, dst;
    if (g_is64) {
        const int* e32 = (const int*)eiv;            // low words of little-endian int64
        src = e32[2 * e];
        dst = e32[2 * (nE + e)];
    } else {
        const int* e32 = (const int*)eiv;
        src = e32[e];
        dst = e32[nE + e];
    }

    float h[HIDD];
    const float4* Cv = (const float4*)(g_C1 + dst * HIDD);
    const float4* Bv = (const float4*)(g_B1 + src * HIDD);
#pragma unroll
    for (int q = 0; q < 16; q++) {
        float4 c4 = Cv[q], b4v = Bv[q];
        h[4 * q + 0] = fmaxf(c4.x + b4v.x, 0.f);
        h[4 * q + 1] = fmaxf(c4.y + b4v.y, 0.f);
        h[4 * q + 2] = fmaxf(c4.z + b4v.z, 0.f);
        h[4 * q + 3] = fmaxf(c4.w + b4v.w, 0.f);
    }

    int* xo = (int*)(g_x1 + dst * HIDD);
    for (int c = 0; c < HIDD; c++) {
        const float4* w = (const float4*)(W2T + c * HIDD);
        float a0 = 0.f, a1 = 0.f, a2 = 0.f, a3 = 0.f;
#pragma unroll
        for (int q = 0; q < 16; q++) {
            float4 ww = w[q];
            a0 += h[4 * q + 0] * ww.x;
            a1 += h[4 * q + 1] * ww.y;
            a2 += h[4 * q + 2] * ww.z;
            a3 += h[4 * q + 3] * ww.w;
        }
        float v = (a0 + a1) + (a2 + a3) + b2s[c];
        // relu + max: x1 init'd to 0, post-ReLU values >= 0 => int atomicMax is order-preserving
        if (v > 0.f) atomicMax(xo + c, __float_as_int(v));
    }
}

// ---------------- row squared norms of x1 (same reduction pattern as knn dot => exact 0 self-dist) ----------------
__global__ void sq_kernel() {
    int i = blockIdx.x * blockDim.x + threadIdx.x;
    if (i >= Nn) return;
    const float4* xv = (const float4*)(g_x1 + i * HIDD);
    float a0 = 0.f, a1 = 0.f, a2 = 0.f, a3 = 0.f;
#pragma unroll
    for (int q = 0; q < 16; q++) {
        float4 v = xv[q];
        a0 += v.x * v.x;
        a1 += v.y * v.y;
        a2 += v.z * v.z;
        a3 += v.w * v.w;
    }
    g_sq[i] = (a0 + a1) + (a2 + a3);
}

// ---------------- brute-force kNN (k=16 incl. self), register top-k ----------------
__global__ void __launch_bounds__(128) knn_kernel() {
    __shared__ float xs[TJ * HIDD];
    __shared__ float sqs[TJ];
    int i = blockIdx.x * blockDim.x + threadIdx.x;  // one row per thread

    float xi[HIDD];
    {
        const float4* xv = (const float4*)(g_x1 + i * HIDD);
#pragma unroll
        for (int q = 0; q < 16; q++) {
            float4 v = xv[q];
            xi[4 * q + 0] = v.x;
            xi[4 * q + 1] = v.y;
            xi[4 * q + 2] = v.z;
            xi[4 * q + 3] = v.w;
        }
    }
    float sqi = g_sq[i];

    float bd[Kk];
    int bi[Kk];
#pragma unroll
    for (int m = 0; m < Kk; m++) {
        bd[m] = 3.4e38f;
        bi[m] = 0;
    }
    float worst = 3.4e38f;

    for (int j0 = 0; j0 < Nn; j0 += TJ) {
        __syncthreads();
        {
            const float4* srcp = (const float4*)(g_x1 + j0 * HIDD);
            float4* dstp = (float4*)xs;
            for (int t = threadIdx.x; t < TJ * HIDD / 4; t += blockDim.x) dstp[t] = srcp[t];
            if (threadIdx.x < TJ) sqs[threadIdx.x] = g_sq[j0 + threadIdx.x];
        }
        __syncthreads();

#pragma unroll 2
        for (int jj = 0; jj < TJ; jj++) {
            const float4* xj = (const float4*)(xs + jj * HIDD);
            float a0 = 0.f, a1 = 0.f, a2 = 0.f, a3 = 0.f;
#pragma unroll
            for (int q = 0; q < 16; q++) {
                float4 v = xj[q];
                a0 += xi[4 * q + 0] * v.x;
                a1 += xi[4 * q + 1] * v.y;
                a2 += xi[4 * q + 2] * v.z;
                a3 += xi[4 * q + 3] * v.w;
            }
            float d = sqi + sqs[jj] - 2.f * ((a0 + a1) + (a2 + a3));
            if (d < worst) {
                // sorted (ascending) register insertion; strict < keeps earlier j on ties
                float cd = d;
                int cj = j0 + jj;
#pragma unroll
                for (int m = 0; m < Kk; m++) {
                    if (cd < bd[m]) {
                        float td = bd[m];
                        bd[m] = cd;
                        cd = td;
                        int ti = bi[m];
                        bi[m] = cj;
                        cj = ti;
                    }
                }
                worst = bd[Kk - 1];
            }
        }
    }
#pragma unroll
    for (int m = 0; m < Kk; m++) g_knn[i * Kk + m] = bi[m];
}

// ---------------- stage-2 per-node precompute on x1 ----------------
__global__ void p2_kernel(const float* __restrict__ W3, const float* __restrict__ b3) {
    int t = blockIdx.x * blockDim.x + threadIdx.x;
    if (t >= Nn * HIDD) return;
    int i = t >> 6, h = t & 63;
    const float* xr = g_x1 + i * HIDD;
    float a = 0.f, b = 0.f;
#pragma unroll 8
    for (int c = 0; c < HIDD; c++) {
        float xc = xr[c];
        a += xc * W3[c * HIDD + h];
        b += xc * W3[(HIDD + c) * HIDD + h];
    }
    g_B2[t] = b;
    g_C2[t] = a - b + b3[h];
}

// ---------------- stage-2 per-edge + max-aggregate (no atomics; shfl over 16-lane groups) ----------------
__global__ void __launch_bounds__(128) e2_kernel(const float* __restrict__ W4,
                                                 const float* __restrict__ b4,
                                                 float* __restrict__ out) {
    __shared__ float W4T[HIDD * HIDD];  // W4T[c][h] = W4[h][c]
    __shared__ float b4s[HIDD];
    for (int t = threadIdx.x; t < HIDD * HIDD; t += blockDim.x) {
        int hh = t >> 6, c = t & 63;
        W4T[c * HIDD + hh] = W4[t];
    }
    if (threadIdx.x < HIDD) b4s[threadIdx.x] = b4[threadIdx.x];
    __syncthreads();

    int lane = threadIdx.x & 31;
    int warp = (blockIdx.x * blockDim.x + threadIdx.x) >> 5;
    int node = warp * 2 + (lane >> 4);  // 2 nodes per warp
    int slot = lane & 15;               // neighbor slot within node
    int j = g_knn[node * Kk + slot];

    float h[HIDD];
    const float4* Cv = (const float4*)(g_C2 + node * HIDD);
    const float4* Bv = (const float4*)(g_B2 + j * HIDD);
#pragma unroll
    for (int q = 0; q < 16; q++) {
        float4 c4 = Cv[q], b4v = Bv[q];
        h[4 * q + 0] = fmaxf(c4.x + b4v.x, 0.f);
        h[4 * q + 1] = fmaxf(c4.y + b4v.y, 0.f);
        h[4 * q + 2] = fmaxf(c4.z + b4v.z, 0.f);
        h[4 * q + 3] = fmaxf(c4.w + b4v.w, 0.f);
    }

    for (int c = 0; c < HIDD; c++) {
        const float4* w = (const float4*)(W4T + c * HIDD);
        float a0 = 0.f, a1 = 0.f, a2 = 0.f, a3 = 0.f;
#pragma unroll
        for (int q = 0; q < 16; q++) {
            float4 ww = w[q];
            a0 += h[4 * q + 0] * ww.x;
            a1 += h[4 * q + 1] * ww.y;
            a2 += h[4 * q + 2] * ww.z;
            a3 += h[4 * q + 3] * ww.w;
        }
        float v = fmaxf((a0 + a1) + (a2 + a3) + b4s[c], 0.f);
        v = fmaxf(v, __shfl_xor_sync(0xffffffffu, v, 8));
        v = fmaxf(v, __shfl_xor_sync(0xffffffffu, v, 4));
        v = fmaxf(v, __shfl_xor_sync(0xffffffffu, v, 2));
        v = fmaxf(v, __shfl_xor_sync(0xffffffffu, v, 1));
        if (slot == 0) out[node * HIDD + c] = v;
    }
}

// ---------------- launch ----------------
extern "C" void kernel_launch(void* const* d_in, const int* in_sizes, int n_in,
                              void* d_out, int out_size) {
    const float* x = (const float*)d_in[0];
    const void* ei = d_in[1];
    // 'k' may or may not be materialized as input #2 (size-1 array); detect.
    int wb = (n_in > 2 && in_sizes[2] == 1) ? 3 : 2;
    const float* W1 = (const float*)d_in[wb + 0];
    const float* b1 = (const float*)d_in[wb + 1];
    const float* W2 = (const float*)d_in[wb + 2];
    const float* b2 = (const float*)d_in[wb + 3];
    const float* W3 = (const float*)d_in[wb + 4];
    const float* b3 = (const float*)d_in[wb + 5];
    const float* W4 = (const float*)d_in[wb + 6];
    const float* b4 = (const float*)d_in[wb + 7];
    int nE = in_sizes[1] / 2;

    detect_kernel<<<1, 256>>>((const int*)ei);
    zero_x1<<<(Nn * HIDD + 255) / 256, 256>>>();
    p1_kernel<<<(Nn * HIDD + 255) / 256, 256>>>(x, W1, b1);
    e1_kernel<<<(nE + 127) / 128, 128>>>(ei, W2, b2, nE);
    sq_kernel<<<(Nn + 127) / 128, 128>>>();
    knn_kernel<<<Nn / 128, 128>>>();
    p2_kernel<<<(Nn * HIDD + 255) / 256, 256>>>(W3, b3);
    e2_kernel<<<Nn / 8, 128>>>(W4, b4, (float*)d_out);
}

// round 10
// speedup vs baseline: 1.4949x; 1.4908x over previous
#include <cuda_runtime.h>

#define Nn 16384
#define HIDD 64
#define Kk 16
#define TJ 32
#define SS 16                 // knn j-range stripes
#define LSTRIPE (Nn / SS)     // 1024 j's per stripe

// ---------------- device scratch (no allocs allowed) ----------------
__device__ __align__(16) float g_B1[Nn * HIDD];
__device__ __align__(16) float g_C1[Nn * HIDD];
__device__ __align__(16) float g_x1[Nn * HIDD];
__device__ __align__(16) float g_B2[Nn * HIDD];
__device__ __align__(16) float g_C2[Nn * HIDD];
__device__ __align__(16) float g_sq[Nn];
__device__ float g_cd[SS * Kk * Nn];   // candidate dists, layout [(s*Kk+m)*Nn + i]
__device__ int   g_ci[SS * Kk * Nn];   // candidate indices, same layout
__device__ int g_knn[Nn * Kk];
__device__ int g_is64;

// ---------------- edge_index dtype detection (int32 vs int64) ----------------
__global__ void detect_kernel(const int* __restrict__ ei32) {
    __shared__ int anynz;
    if (threadIdx.x == 0) anynz = 0;
    __syncthreads();
    // If data is int64 (values < 2^31, nonneg), every odd 32-bit word is 0.
    for (int t = threadIdx.x; t < 2048; t += blockDim.x) {
        if (ei32[2 * t + 1] != 0) anynz = 1;
    }
    __syncthreads();
    if (threadIdx.x == 0) g_is64 = (anynz == 0) ? 1 : 0;
}

// ---------------- init x1 = 0 (segment_max fill + relu>=0 makes this exact) ----------------
__global__ void zero_x1() {
    int t = blockIdx.x * blockDim.x + threadIdx.x;
    if (t < Nn * HIDD) g_x1[t] = 0.f;
}

// ---------------- stage-1 per-node precompute ----------------
// A[i] = xi @ W1[0:3], B[i] = xi @ W1[3:6], C1 = A - B + b1
__global__ void p1_kernel(const float* __restrict__ x, const float* __restrict__ W1,
                          const float* __restrict__ b1) {
    int t = blockIdx.x * blockDim.x + threadIdx.x;
    if (t >= Nn * HIDD) return;
    int i = t >> 6, h = t & 63;
    float x0 = x[i * 3 + 0], x1v = x[i * 3 + 1], x2v = x[i * 3 + 2];
    float a = x0 * W1[0 * HIDD + h] + x1v * W1[1 * HIDD + h] + x2v * W1[2 * HIDD + h];
    float b = x0 * W1[3 * HIDD + h] + x1v * W1[4 * HIDD + h] + x2v * W1[5 * HIDD + h];
    g_B1[t] = b;
    g_C1[t] = a - b + b1[h];
}

// ---------------- stage-1 per-edge: h=relu(C1[dst]+B1[src]); out=relu(h@W2+b2); atomicMax ----------------
__global__ void __launch_bounds__(128) e1_kernel(const void* __restrict__ eiv,
                                                 const float* __restrict__ W2,
                                                 const float* __restrict__ b2, int nE) {
    __shared__ float W2T[HIDD * HIDD];  // W2T[c][h] = W2[h][c]
    __shared__ float b2s[HIDD];
    for (int t = threadIdx.x; t < HIDD * HIDD; t += blockDim.x) {
        int hh = t >> 6, c = t & 63;
        W2T[c * HIDD + hh] = W2[t];
    }
    if (threadIdx.x < HIDD) b2s[threadIdx.x] = b2[threadIdx.x];
    __syncthreads();

    int e = blockIdx.x * blockDim.x + threadIdx.x;
    if (e >= nE) return;
    int src, dst;
    if (g_is64) {
        const int* e32 = (const int*)eiv;            // low words of little-endian int64
        src = e32[2 * e];
        dst = e32[2 * (nE + e)];
    } else {
        const int* e32 = (const int*)eiv;
        src = e32[e];
        dst = e32[nE + e];
    }

    float h[HIDD];
    const float4* Cv = (const float4*)(g_C1 + dst * HIDD);
    const float4* Bv = (const float4*)(g_B1 + src * HIDD);
#pragma unroll
    for (int q = 0; q < 16; q++) {
        float4 c4 = Cv[q], b4v = Bv[q];
        h[4 * q + 0] = fmaxf(c4.x + b4v.x, 0.f);
        h[4 * q + 1] = fmaxf(c4.y + b4v.y, 0.f);
        h[4 * q + 2] = fmaxf(c4.z + b4v.z, 0.f);
        h[4 * q + 3] = fmaxf(c4.w + b4v.w, 0.f);
    }

    int* xo = (int*)(g_x1 + dst * HIDD);
    for (int c = 0; c < HIDD; c++) {
        const float4* w = (const float4*)(W2T + c * HIDD);
        float a0 = 0.f, a1 = 0.f, a2 = 0.f, a3 = 0.f;
#pragma unroll
        for (int q = 0; q < 16; q++) {
            float4 ww = w[q];
            a0 += h[4 * q + 0] * ww.x;
            a1 += h[4 * q + 1] * ww.y;
            a2 += h[4 * q + 2] * ww.z;
            a3 += h[4 * q + 3] * ww.w;
        }
        float v = (a0 + a1) + (a2 + a3) + b2s[c];
        // relu + max: x1 init'd to 0, post-ReLU values >= 0 => int atomicMax is order-preserving
        if (v > 0.f) atomicMax(xo + c, __float_as_int(v));
    }
}

// ---------------- row squared norms of x1 (same reduction pattern as knn dot => exact 0 self-dist) ----------------
__global__ void sq_kernel() {
    int i = blockIdx.x * blockDim.x + threadIdx.x;
    if (i >= Nn) return;
    const float4* xv = (const float4*)(g_x1 + i * HIDD);
    float a0 = 0.f, a1 = 0.f, a2 = 0.f, a3 = 0.f;
#pragma unroll
    for (int q = 0; q < 16; q++) {
        float4 v = xv[q];
        a0 += v.x * v.x;
        a1 += v.y * v.y;
        a2 += v.z * v.z;
        a3 += v.w * v.w;
    }
    g_sq[i] = (a0 + a1) + (a2 + a3);
}

// ---------------- brute-force kNN, stripe-partial: thread = (row i, stripe s) ----------------
// Identical distance arithmetic to the previous passing kernel; only the j-range is split.
__global__ void __launch_bounds__(128) knn_part() {
    __shared__ float xs[TJ * HIDD];
    __shared__ float sqs[TJ];
    int i = blockIdx.x * blockDim.x + threadIdx.x;  // row
    int s = blockIdx.y;                             // stripe
    int jbeg = s * LSTRIPE;

    float xi[HIDD];
    {
        const float4* xv = (const float4*)(g_x1 + i * HIDD);
#pragma unroll
        for (int q = 0; q < 16; q++) {
            float4 v = xv[q];
            xi[4 * q + 0] = v.x;
            xi[4 * q + 1] = v.y;
            xi[4 * q + 2] = v.z;
            xi[4 * q + 3] = v.w;
        }
    }
    float sqi = g_sq[i];

    float bd[Kk];
    int bi[Kk];
#pragma unroll
    for (int m = 0; m < Kk; m++) {
        bd[m] = 3.4e38f;
        bi[m] = 0;
    }
    float worst = 3.4e38f;

    for (int j0 = jbeg; j0 < jbeg + LSTRIPE; j0 += TJ) {
        __syncthreads();
        {
            const float4* srcp = (const float4*)(g_x1 + j0 * HIDD);
            float4* dstp = (float4*)xs;
            for (int t = threadIdx.x; t < TJ * HIDD / 4; t += blockDim.x) dstp[t] = srcp[t];
            if (threadIdx.x < TJ) sqs[threadIdx.x] = g_sq[j0 + threadIdx.x];
        }
        __syncthreads();

#pragma unroll 2
        for (int jj = 0; jj < TJ; jj++) {
            const float4* xj = (const float4*)(xs + jj * HIDD);
            float a0 = 0.f, a1 = 0.f, a2 = 0.f, a3 = 0.f;
#pragma unroll
            for (int q = 0; q < 16; q++) {
                float4 v = xj[q];
                a0 += xi[4 * q + 0] * v.x;
                a1 += xi[4 * q + 1] * v.y;
                a2 += xi[4 * q + 2] * v.z;
                a3 += xi[4 * q + 3] * v.w;
            }
            float d = sqi + sqs[jj] - 2.f * ((a0 + a1) + (a2 + a3));
            if (d < worst) {
                // sorted (ascending) register insertion; strict < keeps earlier j on ties
                float cd = d;
                int cj = j0 + jj;
#pragma unroll
                for (int m = 0; m < Kk; m++) {
                    if (cd < bd[m]) {
                        float td = bd[m];
                        bd[m] = cd;
                        cd = td;
                        int ti = bi[m];
                        bi[m] = cj;
                        cj = ti;
                    }
                }
                worst = bd[Kk - 1];
            }
        }
    }
    // column-major candidate store: coalesced across threads for each m
#pragma unroll
    for (int m = 0; m < Kk; m++) {
        g_cd[(s * Kk + m) * Nn + i] = bd[m];
        g_ci[(s * Kk + m) * Nn + i] = bi[m];
    }
}

// ---------------- merge stripe candidates into final top-16 per row ----------------
// Candidates processed in (stripe-major, then ascending-distance) order; each stripe's
// sorted list is index-stable on ties and lower stripes hold lower j, so strict-<
// insertion reproduces jax top_k's lowest-index tie-breaking exactly.
__global__ void knn_merge() {
    int i = blockIdx.x * blockDim.x + threadIdx.x;
    if (i >= Nn) return;
    float bd[Kk];
    int bi[Kk];
#pragma unroll
    for (int m = 0; m < Kk; m++) {
        bd[m] = 3.4e38f;
        bi[m] = 0;
    }
    float worst = 3.4e38f;
    for (int t = 0; t < SS * Kk; t++) {       // coalesced: stride Nn across threads
        float cd = g_cd[t * Nn + i];
        if (cd < worst) {
            int cj = g_ci[t * Nn + i];
#pragma unroll
            for (int m = 0; m < Kk; m++) {
                if (cd < bd[m]) {
                    float td = bd[m];
                    bd[m] = cd;
                    cd = td;
                    int ti = bi[m];
                    bi[m] = cj;
                    cj = ti;
                }
            }
            worst = bd[Kk - 1];
        }
    }
#pragma unroll
    for (int m = 0; m < Kk; m++) g_knn[i * Kk + m] = bi[m];
}

// ---------------- stage-2 per-node precompute on x1 ----------------
__global__ void p2_kernel(const float* __restrict__ W3, const float* __restrict__ b3) {
    int t = blockIdx.x * blockDim.x + threadIdx.x;
    if (t >= Nn * HIDD) return;
    int i = t >> 6, h = t & 63;
    const float* xr = g_x1 + i * HIDD;
    float a = 0.f, b = 0.f;
#pragma unroll 8
    for (int c = 0; c < HIDD; c++) {
        float xc = xr[c];
        a += xc * W3[c * HIDD + h];
        b += xc * W3[(HIDD + c) * HIDD + h];
    }
    g_B2[t] = b;
    g_C2[t] = a - b + b3[h];
}

// ---------------- stage-2 per-edge + max-aggregate (no atomics; shfl over 16-lane groups) ----------------
__global__ void __launch_bounds__(128) e2_kernel(const float* __restrict__ W4,
                                                 const float* __restrict__ b4,
                                                 float* __restrict__ out) {
    __shared__ float W4T[HIDD * HIDD];  // W4T[c][h] = W4[h][c]
    __shared__ float b4s[HIDD];
    for (int t = threadIdx.x; t < HIDD * HIDD; t += blockDim.x) {
        int hh = t >> 6, c = t & 63;
        W4T[c * HIDD + hh] = W4[t];
    }
    if (threadIdx.x < HIDD) b4s[threadIdx.x] = b4[threadIdx.x];
    __syncthreads();

    int lane = threadIdx.x & 31;
    int warp = (blockIdx.x * blockDim.x + threadIdx.x) >> 5;
    int node = warp * 2 + (lane >> 4);  // 2 nodes per warp
    int slot = lane & 15;               // neighbor slot within node
    int j = g_knn[node * Kk + slot];

    float h[HIDD];
    const float4* Cv = (const float4*)(g_C2 + node * HIDD);
    const float4* Bv = (const float4*)(g_B2 + j * HIDD);
#pragma unroll
    for (int q = 0; q < 16; q++) {
        float4 c4 = Cv[q], b4v = Bv[q];
        h[4 * q + 0] = fmaxf(c4.x + b4v.x, 0.f);
        h[4 * q + 1] = fmaxf(c4.y + b4v.y, 0.f);
        h[4 * q + 2] = fmaxf(c4.z + b4v.z, 0.f);
        h[4 * q + 3] = fmaxf(c4.w + b4v.w, 0.f);
    }

    for (int c = 0; c < HIDD; c++) {
        const float4* w = (const float4*)(W4T + c * HIDD);
        float a0 = 0.f, a1 = 0.f, a2 = 0.f, a3 = 0.f;
#pragma unroll
        for (int q = 0; q < 16; q++) {
            float4 ww = w[q];
            a0 += h[4 * q + 0] * ww.x;
            a1 += h[4 * q + 1] * ww.y;
            a2 += h[4 * q + 2] * ww.z;
            a3 += h[4 * q + 3] * ww.w;
        }
        float v = fmaxf((a0 + a1) + (a2 + a3) + b4s[c], 0.f);
        v = fmaxf(v, __shfl_xor_sync(0xffffffffu, v, 8));
        v = fmaxf(v, __shfl_xor_sync(0xffffffffu, v, 4));
        v = fmaxf(v, __shfl_xor_sync(0xffffffffu, v, 2));
        v = fmaxf(v, __shfl_xor_sync(0xffffffffu, v, 1));
        if (slot == 0) out[node * HIDD + c] = v;
    }
}

// ---------------- launch ----------------
extern "C" void kernel_launch(void* const* d_in, const int* in_sizes, int n_in,
                              void* d_out, int out_size) {
    const float* x = (const float*)d_in[0];
    const void* ei = d_in[1];
    // 'k' may or may not be materialized as input #2 (size-1 array); detect.
    int wb = (n_in > 2 && in_sizes[2] == 1) ? 3 : 2;
    const float* W1 = (const float*)d_in[wb + 0];
    const float* b1 = (const float*)d_in[wb + 1];
    const float* W2 = (const float*)d_in[wb + 2];
    const float* b2 = (const float*)d_in[wb + 3];
    const float* W3 = (const float*)d_in[wb + 4];
    const float* b3 = (const float*)d_in[wb + 5];
    const float* W4 = (const float*)d_in[wb + 6];
    const float* b4 = (const float*)d_in[wb + 7];
    int nE = in_sizes[1] / 2;

    detect_kernel<<<1, 256>>>((const int*)ei);
    zero_x1<<<(Nn * HIDD + 255) / 256, 256>>>();
    p1_kernel<<<(Nn * HIDD + 255) / 256, 256>>>(x, W1, b1);
    e1_kernel<<<(nE + 127) / 128, 128>>>(ei, W2, b2, nE);
    sq_kernel<<<(Nn + 127) / 128, 128>>>();
    {
        dim3 g(Nn / 128, SS);
        knn_part<<<g, 128>>>();
    }
    knn_merge<<<(Nn + 127) / 128, 128>>>();
    p2_kernel<<<(Nn * HIDD + 255) / 256, 256>>>(W3, b3);
    e2_kernel<<<Nn / 8, 128>>>(W4, b4, (float*)d_out);
}

// round 11
// speedup vs baseline: 1.4981x; 1.0022x over previous
#include <cuda_runtime.h>

#define Nn 16384
#define HIDD 64
#define Kk 16
#define TJ 32
#define SS 16                 // knn j-range stripes
#define LSTRIPE (Nn / SS)     // 1024 j's per stripe

// ---------------- device scratch (no allocs allowed) ----------------
__device__ __align__(16) float g_B1[Nn * HIDD];
__device__ __align__(16) float g_C1[Nn * HIDD];
__device__ __align__(16) float g_x1[Nn * HIDD];
__device__ __align__(16) float g_B2[Nn * HIDD];
__device__ __align__(16) float g_C2[Nn * HIDD];
__device__ __align__(16) float g_sq[Nn];
__device__ float g_cd[SS * Kk * Nn];   // candidate dists, layout [(s*Kk+m)*Nn + i]
__device__ int   g_ci[SS * Kk * Nn];   // candidate indices, same layout
__device__ int g_knn[Nn * Kk];
__device__ int g_is64;

// ---------------- edge_index dtype detection (int32 vs int64) ----------------
__global__ void detect_kernel(const int* __restrict__ ei32) {
    __shared__ int anynz;
    if (threadIdx.x == 0) anynz = 0;
    __syncthreads();
    // If data is int64 (values < 2^31, nonneg), every odd 32-bit word is 0.
    for (int t = threadIdx.x; t < 2048; t += blockDim.x) {
        if (ei32[2 * t + 1] != 0) anynz = 1;
    }
    __syncthreads();
    if (threadIdx.x == 0) g_is64 = (anynz == 0) ? 1 : 0;
}

// ---------------- init x1 = 0 (segment_max fill + relu>=0 makes this exact) ----------------
__global__ void zero_x1() {
    int t = blockIdx.x * blockDim.x + threadIdx.x;
    if (t < Nn * HIDD) g_x1[t] = 0.f;
}

// ---------------- stage-1 per-node precompute ----------------
// A[i] = xi @ W1[0:3], B[i] = xi @ W1[3:6], C1 = A - B + b1
__global__ void p1_kernel(const float* __restrict__ x, const float* __restrict__ W1,
                          const float* __restrict__ b1) {
    int t = blockIdx.x * blockDim.x + threadIdx.x;
    if (t >= Nn * HIDD) return;
    int i = t >> 6, h = t & 63;
    float x0 = x[i * 3 + 0], x1v = x[i * 3 + 1], x2v = x[i * 3 + 2];
    float a = x0 * W1[0 * HIDD + h] + x1v * W1[1 * HIDD + h] + x2v * W1[2 * HIDD + h];
    float b = x0 * W1[3 * HIDD + h] + x1v * W1[4 * HIDD + h] + x2v * W1[5 * HIDD + h];
    g_B1[t] = b;
    g_C1[t] = a - b + b1[h];
}

// ---------------- stage-1 per-edge: h=relu(C1[dst]+B1[src]); out=relu(h@W2+b2); atomicMax ----------------
__global__ void __launch_bounds__(128) e1_kernel(const void* __restrict__ eiv,
                                                 const float* __restrict__ W2,
                                                 const float* __restrict__ b2, int nE) {
    __shared__ float W2T[HIDD * HIDD];  // W2T[c][h] = W2[h][c]
    __shared__ float b2s[HIDD];
    for (int t = threadIdx.x; t < HIDD * HIDD; t += blockDim.x) {
        int hh = t >> 6, c = t & 63;
        W2T[c * HIDD + hh] = W2[t];
    }
    if (threadIdx.x < HIDD) b2s[threadIdx.x] = b2[threadIdx.x];
    __syncthreads();

    int e = blockIdx.x * blockDim.x + threadIdx.x;
    if (e >= nE) return;
    int src, dst;
    if (g_is64) {
        const int* e32 = (const int*)eiv;            // low words of little-endian int64
        src = e32[2 * e];
        dst = e32[2 * (nE + e)];
    } else {
        const int* e32 = (const int*)eiv;
        src = e32[e];
        dst = e32[nE + e];
    }

    float h[HIDD];
    const float4* Cv = (const float4*)(g_C1 + dst * HIDD);
    const float4* Bv = (const float4*)(g_B1 + src * HIDD);
#pragma unroll
    for (int q = 0; q < 16; q++) {
        float4 c4 = Cv[q], b4v = Bv[q];
        h[4 * q + 0] = fmaxf(c4.x + b4v.x, 0.f);
        h[4 * q + 1] = fmaxf(c4.y + b4v.y, 0.f);
        h[4 * q + 2] = fmaxf(c4.z + b4v.z, 0.f);
        h[4 * q + 3] = fmaxf(c4.w + b4v.w, 0.f);
    }

    int* xo = (int*)(g_x1 + dst * HIDD);
    for (int c = 0; c < HIDD; c++) {
        const float4* w = (const float4*)(W2T + c * HIDD);
        float a0 = 0.f, a1 = 0.f, a2 = 0.f, a3 = 0.f;
#pragma unroll
        for (int q = 0; q < 16; q++) {
            float4 ww = w[q];
            a0 += h[4 * q + 0] * ww.x;
            a1 += h[4 * q + 1] * ww.y;
            a2 += h[4 * q + 2] * ww.z;
            a3 += h[4 * q + 3] * ww.w;
        }
        float v = (a0 + a1) + (a2 + a3) + b2s[c];
        // relu + max: x1 init'd to 0, post-ReLU values >= 0 => int atomicMax is order-preserving
        if (v > 0.f) atomicMax(xo + c, __float_as_int(v));
    }
}

// ---------------- row squared norms of x1 (same reduction pattern as knn dot => exact 0 self-dist) ----------------
__global__ void sq_kernel() {
    int i = blockIdx.x * blockDim.x + threadIdx.x;
    if (i >= Nn) return;
    const float4* xv = (const float4*)(g_x1 + i * HIDD);
    float a0 = 0.f, a1 = 0.f, a2 = 0.f, a3 = 0.f;
#pragma unroll
    for (int q = 0; q < 16; q++) {
        float4 v = xv[q];
        a0 += v.x * v.x;
        a1 += v.y * v.y;
        a2 += v.z * v.z;
        a3 += v.w * v.w;
    }
    g_sq[i] = (a0 + a1) + (a2 + a3);
}

// ---------------- brute-force kNN, stripe-partial: thread = (row i, stripe s) ----------------
// Identical distance arithmetic to the previous passing kernel; only the j-range is split.
__global__ void __launch_bounds__(128) knn_part() {
    __shared__ float xs[TJ * HIDD];
    __shared__ float sqs[TJ];
    int i = blockIdx.x * blockDim.x + threadIdx.x;  // row
    int s = blockIdx.y;                             // stripe
    int jbeg = s * LSTRIPE;

    float xi[HIDD];
    {
        const float4* xv = (const float4*)(g_x1 + i * HIDD);
#pragma unroll
        for (int q = 0; q < 16; q++) {
            float4 v = xv[q];
            xi[4 * q + 0] = v.x;
            xi[4 * q + 1] = v.y;
            xi[4 * q + 2] = v.z;
            xi[4 * q + 3] = v.w;
        }
    }
    float sqi = g_sq[i];

    float bd[Kk];
    int bi[Kk];
#pragma unroll
    for (int m = 0; m < Kk; m++) {
        bd[m] = 3.4e38f;
        bi[m] = 0;
    }
    float worst = 3.4e38f;

    for (int j0 = jbeg; j0 < jbeg + LSTRIPE; j0 += TJ) {
        __syncthreads();
        {
            const float4* srcp = (const float4*)(g_x1 + j0 * HIDD);
            float4* dstp = (float4*)xs;
            for (int t = threadIdx.x; t < TJ * HIDD / 4; t += blockDim.x) dstp[t] = srcp[t];
            if (threadIdx.x < TJ) sqs[threadIdx.x] = g_sq[j0 + threadIdx.x];
        }
        __syncthreads();

#pragma unroll 2
        for (int jj = 0; jj < TJ; jj++) {
            const float4* xj = (const float4*)(xs + jj * HIDD);
            float a0 = 0.f, a1 = 0.f, a2 = 0.f, a3 = 0.f;
#pragma unroll
            for (int q = 0; q < 16; q++) {
                float4 v = xj[q];
                a0 += xi[4 * q + 0] * v.x;
                a1 += xi[4 * q + 1] * v.y;
                a2 += xi[4 * q + 2] * v.z;
                a3 += xi[4 * q + 3] * v.w;
            }
            float d = sqi + sqs[jj] - 2.f * ((a0 + a1) + (a2 + a3));
            if (d < worst) {
                // sorted (ascending) register insertion; strict < keeps earlier j on ties
                float cd = d;
                int cj = j0 + jj;
#pragma unroll
                for (int m = 0; m < Kk; m++) {
                    if (cd < bd[m]) {
                        float td = bd[m];
                        bd[m] = cd;
                        cd = td;
                        int ti = bi[m];
                        bi[m] = cj;
                        cj = ti;
                    }
                }
                worst = bd[Kk - 1];
            }
        }
    }
    // column-major candidate store: coalesced across threads for each m
#pragma unroll
    for (int m = 0; m < Kk; m++) {
        g_cd[(s * Kk + m) * Nn + i] = bd[m];
        g_ci[(s * Kk + m) * Nn + i] = bi[m];
    }
}

// ---------------- merge stripe candidates into final top-16 per row ----------------
// Candidates processed in (stripe-major, then ascending-distance) order; each stripe's
// sorted list is index-stable on ties and lower stripes hold lower j, so strict-<
// insertion reproduces jax top_k's lowest-index tie-breaking exactly.
__global__ void knn_merge() {
    int i = blockIdx.x * blockDim.x + threadIdx.x;
    if (i >= Nn) return;
    float bd[Kk];
    int bi[Kk];
#pragma unroll
    for (int m = 0; m < Kk; m++) {
        bd[m] = 3.4e38f;
        bi[m] = 0;
    }
    float worst = 3.4e38f;
    for (int t = 0; t < SS * Kk; t++) {       // coalesced: stride Nn across threads
        float cd = g_cd[t * Nn + i];
        if (cd < worst) {
            int cj = g_ci[t * Nn + i];
#pragma unroll
            for (int m = 0; m < Kk; m++) {
                if (cd < bd[m]) {
                    float td = bd[m];
                    bd[m] = cd;
                    cd = td;
                    int ti = bi[m];
                    bi[m] = cj;
                    cj = ti;
                }
            }
            worst = bd[Kk - 1];
        }
    }
#pragma unroll
    for (int m = 0; m < Kk; m++) g_knn[i * Kk + m] = bi[m];
}

// ---------------- stage-2 per-node precompute on x1 ----------------
__global__ void p2_kernel(const float* __restrict__ W3, const float* __restrict__ b3) {
    int t = blockIdx.x * blockDim.x + threadIdx.x;
    if (t >= Nn * HIDD) return;
    int i = t >> 6, h = t & 63;
    const float* xr = g_x1 + i * HIDD;
    float a = 0.f, b = 0.f;
#pragma unroll 8
    for (int c = 0; c < HIDD; c++) {
        float xc = xr[c];
        a += xc * W3[c * HIDD + h];
        b += xc * W3[(HIDD + c) * HIDD + h];
    }
    g_B2[t] = b;
    g_C2[t] = a - b + b3[h];
}

// ---------------- stage-2 per-edge + max-aggregate (no atomics; shfl over 16-lane groups) ----------------
__global__ void __launch_bounds__(128) e2_kernel(const float* __restrict__ W4,
                                                 const float* __restrict__ b4,
                                                 float* __restrict__ out) {
    __shared__ float W4T[HIDD * HIDD];  // W4T[c][h] = W4[h][c]
    __shared__ float b4s[HIDD];
    for (int t = threadIdx.x; t < HIDD * HIDD; t += blockDim.x) {
        int hh = t >> 6, c = t & 63;
        W4T[c * HIDD + hh] = W4[t];
    }
    if (threadIdx.x < HIDD) b4s[threadIdx.x] = b4[threadIdx.x];
    __syncthreads();

    int lane = threadIdx.x & 31;
    int warp = (blockIdx.x * blockDim.x + threadIdx.x) >> 5;
    int node = warp * 2 + (lane >> 4);  // 2 nodes per warp
    int slot = lane & 15;               // neighbor slot within node
    int j = g_knn[node * Kk + slot];

    float h[HIDD];
    const float4* Cv = (const float4*)(g_C2 + node * HIDD);
    const float4* Bv = (const float4*)(g_B2 + j * HIDD);
#pragma unroll
    for (int q = 0; q < 16; q++) {
        float4 c4 = Cv[q], b4v = Bv[q];
        h[4 * q + 0] = fmaxf(c4.x + b4v.x, 0.f);
        h[4 * q + 1] = fmaxf(c4.y + b4v.y, 0.f);
        h[4 * q + 2] = fmaxf(c4.z + b4v.z, 0.f);
        h[4 * q + 3] = fmaxf(c4.w + b4v.w, 0.f);
    }

    for (int c = 0; c < HIDD; c++) {
        const float4* w = (const float4*)(W4T + c * HIDD);
        float a0 = 0.f, a1 = 0.f, a2 = 0.f, a3 = 0.f;
#pragma unroll
        for (int q = 0; q < 16; q++) {
            float4 ww = w[q];
            a0 += h[4 * q + 0] * ww.x;
            a1 += h[4 * q + 1] * ww.y;
            a2 += h[4 * q + 2] * ww.z;
            a3 += h[4 * q + 3] * ww.w;
        }
        float v = fmaxf((a0 + a1) + (a2 + a3) + b4s[c], 0.f);
        v = fmaxf(v, __shfl_xor_sync(0xffffffffu, v, 8));
        v = fmaxf(v, __shfl_xor_sync(0xffffffffu, v, 4));
        v = fmaxf(v, __shfl_xor_sync(0xffffffffu, v, 2));
        v = fmaxf(v, __shfl_xor_sync(0xffffffffu, v, 1));
        if (slot == 0) out[node * HIDD + c] = v;
    }
}

// ---------------- launch ----------------
extern "C" void kernel_launch(void* const* d_in, const int* in_sizes, int n_in,
                              void* d_out, int out_size) {
    const float* x = (const float*)d_in[0];
    const void* ei = d_in[1];
    // 'k' may or may not be materialized as input #2 (size-1 array); detect.
    int wb = (n_in > 2 && in_sizes[2] == 1) ? 3 : 2;
    const float* W1 = (const float*)d_in[wb + 0];
    const float* b1 = (const float*)d_in[wb + 1];
    const float* W2 = (const float*)d_in[wb + 2];
    const float* b2 = (const float*)d_in[wb + 3];
    const float* W3 = (const float*)d_in[wb + 4];
    const float* b3 = (const float*)d_in[wb + 5];
    const float* W4 = (const float*)d_in[wb + 6];
    const float* b4 = (const float*)d_in[wb + 7];
    int nE = in_sizes[1] / 2;

    detect_kernel<<<1, 256>>>((const int*)ei);
    zero_x1<<<(Nn * HIDD + 255) / 256, 256>>>();
    p1_kernel<<<(Nn * HIDD + 255) / 256, 256>>>(x, W1, b1);
    e1_kernel<<<(nE + 127) / 128, 128>>>(ei, W2, b2, nE);
    sq_kernel<<<(Nn + 127) / 128, 128>>>();
    {
        dim3 g(Nn / 128, SS);
        knn_part<<<g, 128>>>();
    }
    knn_merge<<<(Nn + 127) / 128, 128>>>();
    p2_kernel<<<(Nn * HIDD + 255) / 256, 256>>>(W3, b3);
    e2_kernel<<<Nn / 8, 128>>>(W4, b4, (float*)d_out);
}